// round 7
// baseline (speedup 1.0000x reference)
#include <cuda_runtime.h>
#include <stdint.h>

#define NN 65536
#define DD 256
#define KK 4096
#define BM 128
#define BN 128
#define FCAP 65536
#define M2 4.5f
#define QS 22.0f
#define NEG2INV (-2.0f / (QS * QS))

__device__ float g_acc[KK * DD];
__device__ float g_cntf[KK];
__device__ float g_c2[KK];
__device__ unsigned g_cbt[64 * KK];   // int8x4 centers, k4-major: [k4][n]
__device__ float g_loss;
__device__ int g_flagcnt;
__device__ int g_flagrows[FCAP];
__device__ unsigned g_cand[(size_t)FCAP * 48];

__device__ __forceinline__ int q8(float x) {
    int q = __float2int_rn(x * QS);
    return max(-127, min(127, q));
}
__device__ __forceinline__ unsigned pack4(float a, float b, float c, float d) {
    return (unsigned)(q8(a) & 255) | ((unsigned)(q8(b) & 255) << 8) |
           ((unsigned)(q8(c) & 255) << 16) | ((unsigned)q8(d) << 24);
}

#define IMMA(d, a, b0, b1)                                                     \
    asm volatile("mma.sync.aligned.m16n8k32.row.col.s32.s8.s8.s32 "           \
        "{%0,%1,%2,%3}, {%4,%5,%6,%7}, {%8,%9}, {%0,%1,%2,%3};"               \
        : "+r"((d)[0]), "+r"((d)[1]), "+r"((d)[2]), "+r"((d)[3])              \
        : "r"((a).x), "r"((a).y), "r"((a).z), "r"((a).w), "r"(b0), "r"(b1))

// ------------------------------- init -------------------------------
__global__ void init_kernel(const float* __restrict__ centers,
                            const int* __restrict__ counts) {
    int k = blockIdx.x, d = threadIdx.x;
    __shared__ float cs[DD];
    float c = centers[(size_t)k * DD + d];
    float cnt = (float)counts[k];
    g_acc[(size_t)k * DD + d] = cnt * c;
    cs[d] = c;
    __shared__ float red[8];
    float v = c * c;
    #pragma unroll
    for (int o = 16; o > 0; o >>= 1) v += __shfl_down_sync(~0u, v, o);
    if ((d & 31) == 0) red[d >> 5] = v;
    __syncthreads();
    if (d < 64)
        g_cbt[(size_t)d * KK + k] = pack4(cs[4*d], cs[4*d+1], cs[4*d+2], cs[4*d+3]);
    if (d == 0) {
        float s = 0.f;
        #pragma unroll
        for (int w = 0; w < 8; ++w) s += red[w];
        g_c2[k] = s; g_cntf[k] = cnt;
        if (k == 0) { g_loss = 0.f; g_flagcnt = 0; }
    }
}

// ------------------- int8 mma.sync GEMM + top-3 argmin -------------------
// smem u32: A frags [0, 8192), B dbl buf [8192, 8192+2*1056); merge aliases all
#define B_OFF 8192
#define BBUF 1056
#define SMEM_U32 12288
#define GEMM_SMEM (SMEM_U32 * 4)

__global__ void __launch_bounds__(256, 1)
gemm_kernel(const float* __restrict__ emb, float* __restrict__ labels_out) {
    extern __shared__ unsigned smu[];
    const int tid = threadIdx.x, lane = tid & 31, wid = tid >> 5;
    const int warp_m = wid >> 2, warp_n = wid & 3;
    const int g = lane >> 2, t = lane & 3;
    const int row0 = blockIdx.x * BM;

    // ---- stage A: int8 fragment-major ----
    #pragma unroll 4
    for (int it = 0; it < 32; ++it) {
        int i = it * 256 + tid;
        int m = i >> 6, kq = i & 63;
        float4 v = *reinterpret_cast<const float4*>(emb + (size_t)(row0 + m) * DD + kq * 4);
        unsigned pk = pack4(v.x, v.y, v.z, v.w);
        int rr = m & 15, mt = m >> 4;
        int kb = kq * 4, sg = kb >> 5, k32 = kb & 31;
        int j = (rr >> 3) + 2 * (k32 >> 4);
        int ls = (rr & 7) * 4 + ((k32 & 15) >> 2);
        smu[((sg * 8 + mt) * 32 + ls) * 4 + j] = pk;
    }

    float sv1[8], sv2[8], sv3[8]; int si1[8], si2[8], si3[8];
    #pragma unroll
    for (int s = 0; s < 8; ++s) {
        sv1[s] = sv2[s] = sv3[s] = 3.4e38f;
        si1[s] = si2[s] = si3[s] = 0;
    }
    __syncthreads();

    const int pk4r = tid >> 5, pn4 = (tid & 31) * 4;

    #pragma unroll 1
    for (int tile = 0; tile < KK / BN; ++tile) {
        const int j0 = tile * BN;
        int acc[4][4][4];
        #pragma unroll
        for (int a = 0; a < 4; ++a)
            #pragma unroll
            for (int b = 0; b < 4; ++b)
                #pragma unroll
                for (int e = 0; e < 4; ++e) acc[a][b][e] = 0;

        // prologue: chunk 0 -> buf 0
        uint4 pf;
        pf = *reinterpret_cast<const uint4*>(g_cbt + (size_t)pk4r * KK + j0 + pn4);
        *reinterpret_cast<uint4*>(smu + B_OFF + pk4r * 132 + pn4) = pf;
        __syncthreads();

        #pragma unroll 1
        for (int ch = 0; ch < 8; ++ch) {
            const int buf = ch & 1;
            if (ch < 7)
                pf = *reinterpret_cast<const uint4*>(
                    g_cbt + (size_t)((ch + 1) * 8 + pk4r) * KK + j0 + pn4);
            const unsigned* Bb = smu + B_OFF + buf * BBUF;
            uint4 a[4];
            #pragma unroll
            for (int mt = 0; mt < 4; ++mt)
                a[mt] = *(reinterpret_cast<const uint4*>(smu) +
                          ((ch * 8 + warp_m * 4 + mt) * 32 + lane));
            unsigned bb[4][2];
            #pragma unroll
            for (int nt = 0; nt < 4; ++nt) {
                int col = warp_n * 32 + nt * 8 + g;
                bb[nt][0] = Bb[t * 132 + col];
                bb[nt][1] = Bb[(4 + t) * 132 + col];
            }
            #pragma unroll
            for (int mt = 0; mt < 4; ++mt)
                #pragma unroll
                for (int nt = 0; nt < 4; ++nt)
                    IMMA(acc[mt][nt], a[mt], bb[nt][0], bb[nt][1]);
            if (ch < 7)
                *reinterpret_cast<uint4*>(
                    smu + B_OFF + (buf ^ 1) * BBUF + pk4r * 132 + pn4) = pf;
            __syncthreads();
        }

        // per-tile epilogue: v = c2 - 2*dot/S^2, top-3 insert per row-slot
        #pragma unroll
        for (int nt = 0; nt < 4; ++nt) {
            const int cb = j0 + warp_n * 32 + nt * 8 + 2 * t;
            const float c20 = __ldg(&g_c2[cb]);
            const float c21 = __ldg(&g_c2[cb + 1]);
            #pragma unroll
            for (int mt = 0; mt < 4; ++mt) {
                #pragma unroll
                for (int h = 0; h < 2; ++h) {
                    const int s = mt * 2 + h;
                    #pragma unroll
                    for (int e = 0; e < 2; ++e) {
                        float v = fmaf((float)acc[mt][nt][2 * h + e], NEG2INV,
                                       e ? c21 : c20);
                        int c = cb + e;
                        if (v < sv3[s]) {
                            if (v < sv1[s]) {
                                sv3[s] = sv2[s]; si3[s] = si2[s];
                                sv2[s] = sv1[s]; si2[s] = si1[s];
                                sv1[s] = v; si1[s] = c;
                            } else if (v < sv2[s]) {
                                sv3[s] = sv2[s]; si3[s] = si2[s];
                                sv2[s] = v; si2[s] = c;
                            } else { sv3[s] = v; si3[s] = c; }
                        }
                    }
                }
            }
        }
    }

    // ---- merge: alias reduction arrays over smem ----
    __syncthreads();
    float* V1 = (float*)smu;            // [16][128]
    float* V2 = V1 + 2048;
    float* V3 = V2 + 2048;
    int*   I1 = (int*)(V3 + 2048);
    int*   I2 = I1 + 2048;
    int*   I3 = I2 + 2048;
    const int slot = warp_n * 4 + t;
    #pragma unroll
    for (int s = 0; s < 8; ++s) {
        int row = warp_m * 64 + (s >> 1) * 16 + (s & 1) * 8 + g;
        V1[slot * 128 + row] = sv1[s]; I1[slot * 128 + row] = si1[s];
        V2[slot * 128 + row] = sv2[s]; I2[slot * 128 + row] = si2[s];
        V3[slot * 128 + row] = sv3[s]; I3[slot * 128 + row] = si3[s];
    }
    __syncthreads();

    if (tid < 128) {
        float v1 = 3.4e38f, v2 = 3.4e38f; int i1 = 1 << 30;
        #pragma unroll
        for (int s = 0; s < 16; ++s) {
            float a1 = V1[s * 128 + tid], a2 = V2[s * 128 + tid], a3 = V3[s * 128 + tid];
            int   b1 = I1[s * 128 + tid];
            bool lt = (a1 < v1) || (a1 == v1 && b1 < i1);
            if (lt) { v2 = v1; v1 = a1; i1 = b1; } else if (a1 < v2) v2 = a1;
            if (a2 < v2) v2 = a2;
            if (a3 < v2) v2 = a3;
        }
        labels_out[row0 + tid] = (float)i1;
        if (v2 - v1 < M2) {
            int p = atomicAdd(&g_flagcnt, 1);
            g_flagrows[p] = row0 + tid;
            #pragma unroll
            for (int s = 0; s < 16; ++s) {
                g_cand[(size_t)p * 48 + s * 3 + 0] = (unsigned)I1[s * 128 + tid];
                g_cand[(size_t)p * 48 + s * 3 + 1] = (unsigned)I2[s * 128 + tid];
                g_cand[(size_t)p * 48 + s * 3 + 2] = (unsigned)I3[s * 128 + tid];
            }
        }
    }
}

// -------- exact fp32 rescore of flagged rows over 48 candidates --------
__global__ void __launch_bounds__(256)
cand_rescore_kernel(const float* __restrict__ emb, const float* __restrict__ centers,
                    float* __restrict__ labels_out) {
    const int lane = threadIdx.x & 31, w = threadIdx.x >> 5;
    const int cnt = g_flagcnt;
    for (int fi = blockIdx.x * 8 + w; fi < cnt; fi += gridDim.x * 8) {
        const int row = g_flagrows[fi];
        float xv[8];
        #pragma unroll
        for (int q = 0; q < 8; ++q)
            xv[q] = emb[(size_t)row * DD + q * 32 + lane];
        float best = 3.4e38f; int bi = 1 << 30;
        #pragma unroll 1
        for (int q = 0; q < 48; ++q) {
            int c = (int)g_cand[(size_t)fi * 48 + q];
            const float* cp = centers + (size_t)c * DD;
            float dot = 0.f;
            #pragma unroll
            for (int u = 0; u < 8; ++u)
                dot = fmaf(xv[u], __ldg(cp + u * 32 + lane), dot);
            #pragma unroll
            for (int o = 16; o > 0; o >>= 1) dot += __shfl_xor_sync(~0u, dot, o);
            float v = fmaf(-2.f, dot, __ldg(&g_c2[c]));
            if (v < best || (v == best && c < bi)) { best = v; bi = c; }
        }
        if (lane == 0) labels_out[row] = (float)bi;
    }
}

// -------- exact loss + segment sums + counts (final labels) --------
__global__ void __launch_bounds__(256)
scatter_kernel(const float* __restrict__ emb, const float* __restrict__ centers,
               const float* __restrict__ labels) {
    const int t = threadIdx.x;
    const int r0 = blockIdx.x * 64;
    float lsum = 0.f;
    #pragma unroll 1
    for (int r = 0; r < 64; ++r) {
        const int row = r0 + r;
        const int lab = (int)labels[row];
        float x = emb[(size_t)row * DD + t];
        float c = __ldg(&centers[(size_t)lab * DD + t]);
        float d = x - c;
        lsum = fmaf(d, d, lsum);
        atomicAdd(&g_acc[(size_t)lab * DD + t], x);
        if (t == 0) atomicAdd(&g_cntf[lab], 1.0f);
    }
    __shared__ float red[8];
    #pragma unroll
    for (int o = 16; o > 0; o >>= 1) lsum += __shfl_down_sync(~0u, lsum, o);
    if ((t & 31) == 0) red[t >> 5] = lsum;
    __syncthreads();
    if (t == 0) {
        float s = 0.f;
        #pragma unroll
        for (int w = 0; w < 8; ++w) s += red[w];
        atomicAdd(&g_loss, s);
    }
}

__global__ void finalize_kernel(float* __restrict__ out) {
    int k = blockIdx.x, d = threadIdx.x;
    float cnt = g_cntf[k];
    out[(size_t)NN + (size_t)k * DD + d] = g_acc[(size_t)k * DD + d] / cnt;
    if (d == 0) out[(size_t)NN + (size_t)KK * DD + k] = cnt;
    if (k == 0 && d == 0) out[(size_t)NN + (size_t)KK * DD + KK] = g_loss / (float)NN;
}

extern "C" void kernel_launch(void* const* d_in, const int* in_sizes, int n_in,
                              void* d_out, int out_size) {
    const float* emb     = (const float*)d_in[0];
    const float* centers = (const float*)d_in[1];
    const int*   counts  = (const int*)d_in[2];
    float* out = (float*)d_out;

    cudaFuncSetAttribute(gemm_kernel, cudaFuncAttributeMaxDynamicSharedMemorySize, GEMM_SMEM);

    init_kernel<<<KK, 256>>>(centers, counts);
    gemm_kernel<<<NN / BM, 256, GEMM_SMEM>>>(emb, out);
    cand_rescore_kernel<<<1024, 256>>>(emb, centers, out);
    scatter_kernel<<<NN / 64, 256>>>(emb, centers, out);
    finalize_kernel<<<KK, DD>>>(out);
}

// round 8
// speedup vs baseline: 2.2485x; 2.2485x over previous
#include <cuda_runtime.h>
#include <cuda_bf16.h>
#include <stdint.h>

#define NN 65536
#define DD 256
#define KK 4096
#define BM 64
#define BN 128
#define FCAP 65536
#define M2 1.8f

__device__ float g_acc[KK * DD];
__device__ float g_cntf[KK];
__device__ float g_c2[KK];
__device__ unsigned g_cbt[128 * KK];       // bf16x2 centers, k2-major: [k2][n]
__device__ float g_loss;
__device__ int g_flagcnt;
__device__ int g_flagrows[FCAP];
__device__ unsigned g_cand[(size_t)FCAP * 32];

__device__ __forceinline__ unsigned pack_bf2(float lo, float hi) {
    unsigned r; asm("cvt.rn.bf16x2.f32 %0, %1, %2;" : "=r"(r) : "f"(hi), "f"(lo));
    return r;
}

#define MMA16(d, a, b0, b1)                                                    \
    asm volatile("mma.sync.aligned.m16n8k16.row.col.f32.bf16.bf16.f32 "       \
        "{%0,%1,%2,%3}, {%4,%5,%6,%7}, {%8,%9}, {%0,%1,%2,%3};"               \
        : "+f"((d)[0]), "+f"((d)[1]), "+f"((d)[2]), "+f"((d)[3])              \
        : "r"((a).x), "r"((a).y), "r"((a).z), "r"((a).w), "r"(b0), "r"(b1))

// ------------------------------- init -------------------------------
__global__ void init_kernel(const float* __restrict__ centers,
                            const int* __restrict__ counts) {
    int k = blockIdx.x, d = threadIdx.x;
    __shared__ float cs[DD];
    float c = centers[(size_t)k * DD + d];
    float cnt = (float)counts[k];
    g_acc[(size_t)k * DD + d] = cnt * c;
    cs[d] = c;
    __shared__ float red[8];
    float v = c * c;
    #pragma unroll
    for (int o = 16; o > 0; o >>= 1) v += __shfl_down_sync(~0u, v, o);
    if ((d & 31) == 0) red[d >> 5] = v;
    __syncthreads();
    if (d < 128)
        g_cbt[(size_t)d * KK + k] = pack_bf2(cs[2 * d], cs[2 * d + 1]);
    if (d == 0) {
        float s = 0.f;
        #pragma unroll
        for (int w = 0; w < 8; ++w) s += red[w];
        g_c2[k] = s; g_cntf[k] = cnt;
        if (k == 0) { g_loss = 0.f; g_flagcnt = 0; }
    }
}

// ----------- bf16 mma.sync GEMM + top-2 argmin, occupancy 2 -----------
// smem u32: A frags [0, 8192), B dbl buf [8192, 8192 + 2*2176)
#define B_OFF 8192
#define BBUF 2176
#define SMEM_U32 (B_OFF + 2 * BBUF)
#define GEMM_SMEM (SMEM_U32 * 4)

__global__ void __launch_bounds__(256, 2)
gemm_kernel(const float* __restrict__ emb, float* __restrict__ labels_out) {
    extern __shared__ unsigned smu[];
    const int tid = threadIdx.x, lane = tid & 31, wid = tid >> 5;
    const int warp_m = wid >> 2, warp_n = wid & 3;   // 2 x 4 warp grid
    const int g = lane >> 2, t = lane & 3;
    const int row0 = blockIdx.x * BM;

    // ---- stage A: bf16 fragment-major, 64 rows ----
    #pragma unroll 4
    for (int it = 0; it < 16; ++it) {
        int i = it * 256 + tid;
        int m = i >> 6, kq = i & 63;
        float4 v = *reinterpret_cast<const float4*>(emb + (size_t)(row0 + m) * DD + kq * 4);
        unsigned w0 = pack_bf2(v.x, v.y), w1 = pack_bf2(v.z, v.w);
        int rr = m & 15, mt = m >> 4;
        #pragma unroll
        for (int hh = 0; hh < 2; ++hh) {
            int k2 = 2 * kq + hh;
            int sg = k2 >> 3, kw = k2 & 7;
            int L = (rr & 7) * 4 + (kw & 3);
            int j = (rr >> 3) + 2 * (kw >> 2);
            smu[((sg * 4 + mt) * 32 + L) * 4 + j] = hh ? w1 : w0;
        }
    }

    float sv1[4], sv2[4]; int si1[4], si2[4];
    #pragma unroll
    for (int s = 0; s < 4; ++s) { sv1[s] = sv2[s] = 3.4e38f; si1[s] = si2[s] = 0; }
    __syncthreads();

    const int pk2r = tid >> 4, pn8 = (tid & 15) * 8;

    #pragma unroll 1
    for (int tile = 0; tile < KK / BN; ++tile) {
        const int j0 = tile * BN;
        float acc[2][4][4];
        #pragma unroll
        for (int a = 0; a < 2; ++a)
            #pragma unroll
            for (int b = 0; b < 4; ++b)
                #pragma unroll
                for (int e = 0; e < 4; ++e) acc[a][b][e] = 0.f;

        // prologue: chunk 0 -> buf 0
        uint4 p0, p1;
        {
            const uint4* src = reinterpret_cast<const uint4*>(
                g_cbt + (size_t)pk2r * KK + j0 + pn8);
            p0 = src[0]; p1 = src[1];
            uint4* dst = reinterpret_cast<uint4*>(smu + B_OFF + pk2r * 136 + pn8);
            dst[0] = p0; dst[1] = p1;
        }
        __syncthreads();

        #pragma unroll 1
        for (int ch = 0; ch < 8; ++ch) {
            const int buf = ch & 1;
            if (ch < 7) {
                const uint4* src = reinterpret_cast<const uint4*>(
                    g_cbt + (size_t)((ch + 1) * 16 + pk2r) * KK + j0 + pn8);
                p0 = src[0]; p1 = src[1];
            }
            const unsigned* Bb = smu + B_OFF + buf * BBUF;
            #pragma unroll
            for (int s4 = 0; s4 < 2; ++s4) {
                const int sg = ch * 2 + s4;
                uint4 a[2];
                #pragma unroll
                for (int mi = 0; mi < 2; ++mi)
                    a[mi] = *(reinterpret_cast<const uint4*>(smu) +
                              ((sg * 4 + warp_m * 2 + mi) * 32 + lane));
                unsigned bb[4][2];
                #pragma unroll
                for (int nt = 0; nt < 4; ++nt) {
                    int col = warp_n * 32 + nt * 8 + g;
                    bb[nt][0] = Bb[(s4 * 8 + t) * 136 + col];
                    bb[nt][1] = Bb[(s4 * 8 + t + 4) * 136 + col];
                }
                #pragma unroll
                for (int mi = 0; mi < 2; ++mi)
                    #pragma unroll
                    for (int nt = 0; nt < 4; ++nt)
                        MMA16(acc[mi][nt], a[mi], bb[nt][0], bb[nt][1]);
            }
            if (ch < 7) {
                uint4* dst = reinterpret_cast<uint4*>(
                    smu + B_OFF + (buf ^ 1) * BBUF + pk2r * 136 + pn8);
                dst[0] = p0; dst[1] = p1;
            }
            __syncthreads();
        }

        // per-tile epilogue: v = c2 - 2*dot, top-2 insert per row-slot
        #pragma unroll
        for (int nt = 0; nt < 4; ++nt) {
            const int cb = j0 + warp_n * 32 + nt * 8 + 2 * t;
            const float c20 = __ldg(&g_c2[cb]);
            const float c21 = __ldg(&g_c2[cb + 1]);
            #pragma unroll
            for (int mi = 0; mi < 2; ++mi) {
                #pragma unroll
                for (int h = 0; h < 2; ++h) {
                    const int s = mi * 2 + h;
                    #pragma unroll
                    for (int e = 0; e < 2; ++e) {
                        float v = fmaf(-2.f, acc[mi][nt][2 * h + e], e ? c21 : c20);
                        int c = cb + e;
                        if (v < sv2[s]) {
                            if (v < sv1[s]) {
                                sv2[s] = sv1[s]; si2[s] = si1[s];
                                sv1[s] = v; si1[s] = c;
                            } else { sv2[s] = v; si2[s] = c; }
                        }
                    }
                }
            }
        }
    }

    // ---- merge: alias reduction arrays over A smem region ----
    __syncthreads();
    float* V1 = (float*)smu;            // [16][64]
    float* V2 = V1 + 1024;
    int*   I1 = (int*)(V2 + 1024);
    int*   I2 = I1 + 1024;
    const int slot = warp_n * 4 + t;
    #pragma unroll
    for (int s = 0; s < 4; ++s) {
        int row = warp_m * 32 + (s >> 1) * 16 + (s & 1) * 8 + g;
        V1[slot * 64 + row] = sv1[s]; I1[slot * 64 + row] = si1[s];
        V2[slot * 64 + row] = sv2[s]; I2[slot * 64 + row] = si2[s];
    }
    __syncthreads();

    if (tid < 64) {
        float v1 = 3.4e38f, v2 = 3.4e38f; int i1 = 1 << 30;
        #pragma unroll
        for (int s = 0; s < 16; ++s) {
            float a1 = V1[s * 64 + tid], a2 = V2[s * 64 + tid];
            int   b1 = I1[s * 64 + tid];
            bool lt = (a1 < v1) || (a1 == v1 && b1 < i1);
            if (lt) { v2 = v1; v1 = a1; i1 = b1; } else if (a1 < v2) v2 = a1;
            if (a2 < v2) v2 = a2;
        }
        labels_out[row0 + tid] = (float)i1;
        if (v2 - v1 < M2) {
            int p = atomicAdd(&g_flagcnt, 1);
            g_flagrows[p] = row0 + tid;
            #pragma unroll
            for (int s = 0; s < 16; ++s) {
                g_cand[(size_t)p * 32 + s * 2 + 0] = (unsigned)I1[s * 64 + tid];
                g_cand[(size_t)p * 32 + s * 2 + 1] = (unsigned)I2[s * 64 + tid];
            }
        }
    }
}

// -------- exact fp32 rescore of flagged rows over 32 candidates --------
__global__ void __launch_bounds__(256)
cand_rescore_kernel(const float* __restrict__ emb, const float* __restrict__ centers,
                    float* __restrict__ labels_out) {
    const int lane = threadIdx.x & 31, w = threadIdx.x >> 5;
    const int cnt = g_flagcnt;
    for (int fi = blockIdx.x * 8 + w; fi < cnt; fi += gridDim.x * 8) {
        const int row = g_flagrows[fi];
        float xv[8];
        #pragma unroll
        for (int q = 0; q < 8; ++q)
            xv[q] = emb[(size_t)row * DD + q * 32 + lane];
        float best = 3.4e38f; int bi = 1 << 30;
        #pragma unroll 1
        for (int q = 0; q < 32; ++q) {
            int c = (int)g_cand[(size_t)fi * 32 + q];
            const float* cp = centers + (size_t)c * DD;
            float dot = 0.f;
            #pragma unroll
            for (int u = 0; u < 8; ++u)
                dot = fmaf(xv[u], __ldg(cp + u * 32 + lane), dot);
            #pragma unroll
            for (int o = 16; o > 0; o >>= 1) dot += __shfl_xor_sync(~0u, dot, o);
            float v = fmaf(-2.f, dot, __ldg(&g_c2[c]));
            if (v < best || (v == best && c < bi)) { best = v; bi = c; }
        }
        if (lane == 0) labels_out[row] = (float)bi;
    }
}

// -------- exact loss + segment sums + counts (final labels) --------
__global__ void __launch_bounds__(256)
scatter_kernel(const float* __restrict__ emb, const float* __restrict__ centers,
               const float* __restrict__ labels) {
    const int t = threadIdx.x;
    const int r0 = blockIdx.x * 64;
    float lsum = 0.f;
    #pragma unroll 1
    for (int r = 0; r < 64; ++r) {
        const int row = r0 + r;
        const int lab = (int)labels[row];
        float x = emb[(size_t)row * DD + t];
        float c = __ldg(&centers[(size_t)lab * DD + t]);
        float d = x - c;
        lsum = fmaf(d, d, lsum);
        atomicAdd(&g_acc[(size_t)lab * DD + t], x);
        if (t == 0) atomicAdd(&g_cntf[lab], 1.0f);
    }
    __shared__ float red[8];
    #pragma unroll
    for (int o = 16; o > 0; o >>= 1) lsum += __shfl_down_sync(~0u, lsum, o);
    if ((t & 31) == 0) red[t >> 5] = lsum;
    __syncthreads();
    if (t == 0) {
        float s = 0.f;
        #pragma unroll
        for (int w = 0; w < 8; ++w) s += red[w];
        atomicAdd(&g_loss, s);
    }
}

__global__ void finalize_kernel(float* __restrict__ out) {
    int k = blockIdx.x, d = threadIdx.x;
    float cnt = g_cntf[k];
    out[(size_t)NN + (size_t)k * DD + d] = g_acc[(size_t)k * DD + d] / cnt;
    if (d == 0) out[(size_t)NN + (size_t)KK * DD + k] = cnt;
    if (k == 0 && d == 0) out[(size_t)NN + (size_t)KK * DD + KK] = g_loss / (float)NN;
}

extern "C" void kernel_launch(void* const* d_in, const int* in_sizes, int n_in,
                              void* d_out, int out_size) {
    const float* emb     = (const float*)d_in[0];
    const float* centers = (const float*)d_in[1];
    const int*   counts  = (const int*)d_in[2];
    float* out = (float*)d_out;

    cudaFuncSetAttribute(gemm_kernel, cudaFuncAttributeMaxDynamicSharedMemorySize, GEMM_SMEM);

    init_kernel<<<KK, 256>>>(centers, counts);
    gemm_kernel<<<NN / BM, 256, GEMM_SMEM>>>(emb, out);
    cand_rescore_kernel<<<1024, 256>>>(emb, centers, out);
    scatter_kernel<<<NN / 64, 256>>>(emb, centers, out);
    finalize_kernel<<<KK, DD>>>(out);
}

// round 9
// speedup vs baseline: 2.2813x; 1.0146x over previous
#include <cuda_runtime.h>
#include <cuda_bf16.h>
#include <stdint.h>

#define NN 65536
#define DD 256
#define KK 4096
#define BM 64
#define BN 128
#define FCAP 65536
#define M2 1.8f

__device__ float g_acc[KK * DD];
__device__ float g_cntf[KK];
__device__ float g_c2[KK];
__device__ unsigned g_cbt[128 * KK];       // bf16x2 centers, k2-major: [k2][n]
__device__ float g_loss;
__device__ int g_flagcnt;
__device__ int g_flagrows[FCAP];
__device__ unsigned g_cand[(size_t)FCAP * 32];

__device__ __forceinline__ unsigned pack_bf2(float lo, float hi) {
    unsigned r; asm("cvt.rn.bf16x2.f32 %0, %1, %2;" : "=r"(r) : "f"(hi), "f"(lo));
    return r;
}

#define MMA16(d, a, b0, b1)                                                    \
    asm volatile("mma.sync.aligned.m16n8k16.row.col.f32.bf16.bf16.f32 "       \
        "{%0,%1,%2,%3}, {%4,%5,%6,%7}, {%8,%9}, {%0,%1,%2,%3};"               \
        : "+f"((d)[0]), "+f"((d)[1]), "+f"((d)[2]), "+f"((d)[3])              \
        : "r"((a).x), "r"((a).y), "r"((a).z), "r"((a).w), "r"(b0), "r"(b1))

// ------------------------------- init -------------------------------
__global__ void init_kernel(const float* __restrict__ centers,
                            const int* __restrict__ counts) {
    int k = blockIdx.x, d = threadIdx.x;
    __shared__ float cs[DD];
    float c = centers[(size_t)k * DD + d];
    float cnt = (float)counts[k];
    g_acc[(size_t)k * DD + d] = cnt * c;
    cs[d] = c;
    __shared__ float red[8];
    float v = c * c;
    #pragma unroll
    for (int o = 16; o > 0; o >>= 1) v += __shfl_down_sync(~0u, v, o);
    if ((d & 31) == 0) red[d >> 5] = v;
    __syncthreads();
    if (d < 128)
        g_cbt[(size_t)d * KK + k] = pack_bf2(cs[2 * d], cs[2 * d + 1]);
    if (d == 0) {
        float s = 0.f;
        #pragma unroll
        for (int w = 0; w < 8; ++w) s += red[w];
        g_c2[k] = s; g_cntf[k] = cnt;
        if (k == 0) { g_loss = 0.f; g_flagcnt = 0; }
    }
}

// ----------- bf16 mma.sync GEMM + top-2 argmin, occupancy 3 -----------
// smem u32: A frags [0, 8192), B dbl buf [8192, 8192 + 2*2176)
#define B_OFF 8192
#define BBUF 2176
#define SMEM_U32 (B_OFF + 2 * BBUF)
#define GEMM_SMEM (SMEM_U32 * 4)

__global__ void __launch_bounds__(256, 3)
gemm_kernel(const float* __restrict__ emb, float* __restrict__ labels_out) {
    extern __shared__ unsigned smu[];
    const int tid = threadIdx.x, lane = tid & 31, wid = tid >> 5;
    const int warp_m = wid >> 2, warp_n = wid & 3;   // 2 x 4 warp grid
    const int g = lane >> 2, t = lane & 3;
    const int row0 = blockIdx.x * BM;

    // ---- stage A: bf16 fragment-major, 64 rows ----
    #pragma unroll 4
    for (int it = 0; it < 16; ++it) {
        int i = it * 256 + tid;
        int m = i >> 6, kq = i & 63;
        float4 v = *reinterpret_cast<const float4*>(emb + (size_t)(row0 + m) * DD + kq * 4);
        unsigned w0 = pack_bf2(v.x, v.y), w1 = pack_bf2(v.z, v.w);
        int rr = m & 15, mt = m >> 4;
        #pragma unroll
        for (int hh = 0; hh < 2; ++hh) {
            int k2 = 2 * kq + hh;
            int sg = k2 >> 3, kw = k2 & 7;
            int L = (rr & 7) * 4 + (kw & 3);
            int j = (rr >> 3) + 2 * (kw >> 2);
            smu[((sg * 4 + mt) * 32 + L) * 4 + j] = hh ? w1 : w0;
        }
    }

    float sv1[4], sv2[4]; int si1[4], si2[4];
    #pragma unroll
    for (int s = 0; s < 4; ++s) { sv1[s] = sv2[s] = 3.4e38f; si1[s] = si2[s] = 0; }
    __syncthreads();

    const int pk2r = tid >> 4, pn8 = (tid & 15) * 8;

    #pragma unroll 1
    for (int tile = 0; tile < KK / BN; ++tile) {
        const int j0 = tile * BN;
        float acc[2][4][4];
        #pragma unroll
        for (int a = 0; a < 2; ++a)
            #pragma unroll
            for (int b = 0; b < 4; ++b)
                #pragma unroll
                for (int e = 0; e < 4; ++e) acc[a][b][e] = 0.f;

        // prologue: chunk 0 -> buf 0
        uint4 p0, p1;
        {
            const uint4* src = reinterpret_cast<const uint4*>(
                g_cbt + (size_t)pk2r * KK + j0 + pn8);
            p0 = src[0]; p1 = src[1];
            uint4* dst = reinterpret_cast<uint4*>(smu + B_OFF + pk2r * 136 + pn8);
            dst[0] = p0; dst[1] = p1;
        }
        __syncthreads();

        #pragma unroll 1
        for (int ch = 0; ch < 8; ++ch) {
            const int buf = ch & 1;
            if (ch < 7) {
                const uint4* src = reinterpret_cast<const uint4*>(
                    g_cbt + (size_t)((ch + 1) * 16 + pk2r) * KK + j0 + pn8);
                p0 = src[0]; p1 = src[1];
            }
            const unsigned* Bb = smu + B_OFF + buf * BBUF;
            #pragma unroll
            for (int s4 = 0; s4 < 2; ++s4) {
                const int sg = ch * 2 + s4;
                uint4 a[2];
                #pragma unroll
                for (int mi = 0; mi < 2; ++mi)
                    a[mi] = *(reinterpret_cast<const uint4*>(smu) +
                              ((sg * 4 + warp_m * 2 + mi) * 32 + lane));
                unsigned bb[4][2];
                #pragma unroll
                for (int nt = 0; nt < 4; ++nt) {
                    int col = warp_n * 32 + nt * 8 + g;
                    bb[nt][0] = Bb[(s4 * 8 + t) * 136 + col];
                    bb[nt][1] = Bb[(s4 * 8 + t + 4) * 136 + col];
                }
                #pragma unroll
                for (int mi = 0; mi < 2; ++mi)
                    #pragma unroll
                    for (int nt = 0; nt < 4; ++nt)
                        MMA16(acc[mi][nt], a[mi], bb[nt][0], bb[nt][1]);
            }
            if (ch < 7) {
                uint4* dst = reinterpret_cast<uint4*>(
                    smu + B_OFF + (buf ^ 1) * BBUF + pk2r * 136 + pn8);
                dst[0] = p0; dst[1] = p1;
            }
            __syncthreads();
        }

        // per-tile epilogue: v = c2 - 2*dot, top-2 insert per row-slot
        #pragma unroll
        for (int nt = 0; nt < 4; ++nt) {
            const int cb = j0 + warp_n * 32 + nt * 8 + 2 * t;
            const float c20 = __ldg(&g_c2[cb]);
            const float c21 = __ldg(&g_c2[cb + 1]);
            #pragma unroll
            for (int mi = 0; mi < 2; ++mi) {
                #pragma unroll
                for (int h = 0; h < 2; ++h) {
                    const int s = mi * 2 + h;
                    #pragma unroll
                    for (int e = 0; e < 2; ++e) {
                        float v = fmaf(-2.f, acc[mi][nt][2 * h + e], e ? c21 : c20);
                        int c = cb + e;
                        if (v < sv2[s]) {
                            if (v < sv1[s]) {
                                sv2[s] = sv1[s]; si2[s] = si1[s];
                                sv1[s] = v; si1[s] = c;
                            } else { sv2[s] = v; si2[s] = c; }
                        }
                    }
                }
            }
        }
    }

    // ---- merge: alias reduction arrays over A smem region ----
    __syncthreads();
    float* V1 = (float*)smu;            // [16][64]
    float* V2 = V1 + 1024;
    int*   I1 = (int*)(V2 + 1024);
    int*   I2 = I1 + 1024;
    const int slot = warp_n * 4 + t;
    #pragma unroll
    for (int s = 0; s < 4; ++s) {
        int row = warp_m * 32 + (s >> 1) * 16 + (s & 1) * 8 + g;
        V1[slot * 64 + row] = sv1[s]; I1[slot * 64 + row] = si1[s];
        V2[slot * 64 + row] = sv2[s]; I2[slot * 64 + row] = si2[s];
    }
    __syncthreads();

    if (tid < 64) {
        float v1 = 3.4e38f, v2 = 3.4e38f; int i1 = 1 << 30;
        #pragma unroll
        for (int s = 0; s < 16; ++s) {
            float a1 = V1[s * 64 + tid], a2 = V2[s * 64 + tid];
            int   b1 = I1[s * 64 + tid];
            bool lt = (a1 < v1) || (a1 == v1 && b1 < i1);
            if (lt) { v2 = v1; v1 = a1; i1 = b1; } else if (a1 < v2) v2 = a1;
            if (a2 < v2) v2 = a2;
        }
        labels_out[row0 + tid] = (float)i1;
        if (v2 - v1 < M2) {
            int p = atomicAdd(&g_flagcnt, 1);
            g_flagrows[p] = row0 + tid;
            #pragma unroll
            for (int s = 0; s < 16; ++s) {
                g_cand[(size_t)p * 32 + s * 2 + 0] = (unsigned)I1[s * 64 + tid];
                g_cand[(size_t)p * 32 + s * 2 + 1] = (unsigned)I2[s * 64 + tid];
            }
        }
    }
}

// -------- exact fp32 rescore of flagged rows over 32 candidates --------
__global__ void __launch_bounds__(256)
cand_rescore_kernel(const float* __restrict__ emb, const float* __restrict__ centers,
                    float* __restrict__ labels_out) {
    const int lane = threadIdx.x & 31, w = threadIdx.x >> 5;
    const int cnt = g_flagcnt;
    for (int fi = blockIdx.x * 8 + w; fi < cnt; fi += gridDim.x * 8) {
        const int row = g_flagrows[fi];
        float xv[8];
        #pragma unroll
        for (int q = 0; q < 8; ++q)
            xv[q] = emb[(size_t)row * DD + q * 32 + lane];
        float best = 3.4e38f; int bi = 1 << 30;
        #pragma unroll 1
        for (int q = 0; q < 32; ++q) {
            int c = (int)g_cand[(size_t)fi * 32 + q];
            const float* cp = centers + (size_t)c * DD;
            float dot = 0.f;
            #pragma unroll
            for (int u = 0; u < 8; ++u)
                dot = fmaf(xv[u], __ldg(cp + u * 32 + lane), dot);
            #pragma unroll
            for (int o = 16; o > 0; o >>= 1) dot += __shfl_xor_sync(~0u, dot, o);
            float v = fmaf(-2.f, dot, __ldg(&g_c2[c]));
            if (v < best || (v == best && c < bi)) { best = v; bi = c; }
        }
        if (lane == 0) labels_out[row] = (float)bi;
    }
}

// -------- exact loss + segment sums + counts (final labels) --------
__global__ void __launch_bounds__(256)
scatter_kernel(const float* __restrict__ emb, const float* __restrict__ centers,
               const float* __restrict__ labels) {
    const int t = threadIdx.x;
    const int r0 = blockIdx.x * 64;
    float lsum = 0.f;
    #pragma unroll 1
    for (int r = 0; r < 64; ++r) {
        const int row = r0 + r;
        const int lab = (int)labels[row];
        float x = emb[(size_t)row * DD + t];
        float c = __ldg(&centers[(size_t)lab * DD + t]);
        float d = x - c;
        lsum = fmaf(d, d, lsum);
        atomicAdd(&g_acc[(size_t)lab * DD + t], x);
        if (t == 0) atomicAdd(&g_cntf[lab], 1.0f);
    }
    __shared__ float red[8];
    #pragma unroll
    for (int o = 16; o > 0; o >>= 1) lsum += __shfl_down_sync(~0u, lsum, o);
    if ((t & 31) == 0) red[t >> 5] = lsum;
    __syncthreads();
    if (t == 0) {
        float s = 0.f;
        #pragma unroll
        for (int w = 0; w < 8; ++w) s += red[w];
        atomicAdd(&g_loss, s);
    }
}

__global__ void finalize_kernel(float* __restrict__ out) {
    int k = blockIdx.x, d = threadIdx.x;
    float cnt = g_cntf[k];
    out[(size_t)NN + (size_t)k * DD + d] = g_acc[(size_t)k * DD + d] / cnt;
    if (d == 0) out[(size_t)NN + (size_t)KK * DD + k] = cnt;
    if (k == 0 && d == 0) out[(size_t)NN + (size_t)KK * DD + KK] = g_loss / (float)NN;
}

extern "C" void kernel_launch(void* const* d_in, const int* in_sizes, int n_in,
                              void* d_out, int out_size) {
    const float* emb     = (const float*)d_in[0];
    const float* centers = (const float*)d_in[1];
    const int*   counts  = (const int*)d_in[2];
    float* out = (float*)d_out;

    cudaFuncSetAttribute(gemm_kernel, cudaFuncAttributeMaxDynamicSharedMemorySize, GEMM_SMEM);

    init_kernel<<<KK, 256>>>(centers, counts);
    gemm_kernel<<<NN / BM, 256, GEMM_SMEM>>>(emb, out);
    cand_rescore_kernel<<<1024, 256>>>(emb, centers, out);
    scatter_kernel<<<NN / 64, 256>>>(emb, centers, out);
    finalize_kernel<<<KK, DD>>>(out);
}

// round 10
// speedup vs baseline: 2.2948x; 1.0059x over previous
#include <cuda_runtime.h>
#include <cuda_bf16.h>
#include <stdint.h>

#define NN 65536
#define DD 256
#define KK 4096
#define BM 64
#define BN 128
#define FCAP 65536
#define M2 1.8f

__device__ float g_acc[KK * DD];
__device__ float g_cntf[KK];
__device__ float g_c2[KK];
__device__ unsigned g_cbt[128 * KK];       // bf16x2 centers, k2-major: [k2][n]
__device__ float g_loss;
__device__ int g_flagcnt;
__device__ int g_flagrows[FCAP];
__device__ unsigned g_cand[(size_t)FCAP * 32];
__device__ int g_fixcnt;
__device__ int g_fixrow[FCAP];
__device__ int g_fixold[FCAP];

__device__ __forceinline__ unsigned pack_bf2(float lo, float hi) {
    unsigned r; asm("cvt.rn.bf16x2.f32 %0, %1, %2;" : "=r"(r) : "f"(hi), "f"(lo));
    return r;
}

#define MMA16(d, a, b0, b1)                                                    \
    asm volatile("mma.sync.aligned.m16n8k16.row.col.f32.bf16.bf16.f32 "       \
        "{%0,%1,%2,%3}, {%4,%5,%6,%7}, {%8,%9}, {%0,%1,%2,%3};"               \
        : "+f"((d)[0]), "+f"((d)[1]), "+f"((d)[2]), "+f"((d)[3])              \
        : "r"((a).x), "r"((a).y), "r"((a).z), "r"((a).w), "r"(b0), "r"(b1))

// ------------------------------- init -------------------------------
__global__ void init_kernel(const float* __restrict__ centers,
                            const int* __restrict__ counts) {
    int k = blockIdx.x, d = threadIdx.x;
    __shared__ float cs[DD];
    float c = centers[(size_t)k * DD + d];
    float cnt = (float)counts[k];
    g_acc[(size_t)k * DD + d] = cnt * c;
    cs[d] = c;
    __shared__ float red[8];
    float v = c * c;
    #pragma unroll
    for (int o = 16; o > 0; o >>= 1) v += __shfl_down_sync(~0u, v, o);
    if ((d & 31) == 0) red[d >> 5] = v;
    __syncthreads();
    if (d < 128)
        g_cbt[(size_t)d * KK + k] = pack_bf2(cs[2 * d], cs[2 * d + 1]);
    if (d == 0) {
        float s = 0.f;
        #pragma unroll
        for (int w = 0; w < 8; ++w) s += red[w];
        g_c2[k] = s; g_cntf[k] = cnt;
        if (k == 0) { g_loss = 0.f; g_flagcnt = 0; g_fixcnt = 0; }
    }
}

// --- bf16 mma.sync GEMM + top-2 argmin + fused scatter, occupancy 3 ---
#define B_OFF 8192
#define BBUF 2176
#define SMEM_U32 (B_OFF + 2 * BBUF)
#define GEMM_SMEM (SMEM_U32 * 4)

__global__ void __launch_bounds__(256, 3)
gemm_kernel(const float* __restrict__ emb, const float* __restrict__ centers,
            float* __restrict__ labels_out) {
    extern __shared__ unsigned smu[];
    const int tid = threadIdx.x, lane = tid & 31, wid = tid >> 5;
    const int warp_m = wid >> 2, warp_n = wid & 3;   // 2 x 4 warp grid
    const int g = lane >> 2, t = lane & 3;
    const int row0 = blockIdx.x * BM;

    // ---- stage A: bf16 fragment-major, 64 rows ----
    #pragma unroll 4
    for (int it = 0; it < 16; ++it) {
        int i = it * 256 + tid;
        int m = i >> 6, kq = i & 63;
        float4 v = *reinterpret_cast<const float4*>(emb + (size_t)(row0 + m) * DD + kq * 4);
        unsigned w0 = pack_bf2(v.x, v.y), w1 = pack_bf2(v.z, v.w);
        int rr = m & 15, mt = m >> 4;
        #pragma unroll
        for (int hh = 0; hh < 2; ++hh) {
            int k2 = 2 * kq + hh;
            int sg = k2 >> 3, kw = k2 & 7;
            int L = (rr & 7) * 4 + (kw & 3);
            int j = (rr >> 3) + 2 * (kw >> 2);
            smu[((sg * 4 + mt) * 32 + L) * 4 + j] = hh ? w1 : w0;
        }
    }

    float sv1[4], sv2[4]; int si1[4], si2[4];
    #pragma unroll
    for (int s = 0; s < 4; ++s) { sv1[s] = sv2[s] = 3.4e38f; si1[s] = si2[s] = 0; }
    __syncthreads();

    const int pk2r = tid >> 4, pn8 = (tid & 15) * 8;

    #pragma unroll 1
    for (int tile = 0; tile < KK / BN; ++tile) {
        const int j0 = tile * BN;
        float acc[2][4][4];
        #pragma unroll
        for (int a = 0; a < 2; ++a)
            #pragma unroll
            for (int b = 0; b < 4; ++b)
                #pragma unroll
                for (int e = 0; e < 4; ++e) acc[a][b][e] = 0.f;

        uint4 p0, p1;
        {
            const uint4* src = reinterpret_cast<const uint4*>(
                g_cbt + (size_t)pk2r * KK + j0 + pn8);
            p0 = src[0]; p1 = src[1];
            uint4* dst = reinterpret_cast<uint4*>(smu + B_OFF + pk2r * 136 + pn8);
            dst[0] = p0; dst[1] = p1;
        }
        __syncthreads();

        #pragma unroll 1
        for (int ch = 0; ch < 8; ++ch) {
            const int buf = ch & 1;
            if (ch < 7) {
                const uint4* src = reinterpret_cast<const uint4*>(
                    g_cbt + (size_t)((ch + 1) * 16 + pk2r) * KK + j0 + pn8);
                p0 = src[0]; p1 = src[1];
            }
            const unsigned* Bb = smu + B_OFF + buf * BBUF;
            #pragma unroll
            for (int s4 = 0; s4 < 2; ++s4) {
                const int sg = ch * 2 + s4;
                uint4 a[2];
                #pragma unroll
                for (int mi = 0; mi < 2; ++mi)
                    a[mi] = *(reinterpret_cast<const uint4*>(smu) +
                              ((sg * 4 + warp_m * 2 + mi) * 32 + lane));
                unsigned bb[4][2];
                #pragma unroll
                for (int nt = 0; nt < 4; ++nt) {
                    int col = warp_n * 32 + nt * 8 + g;
                    bb[nt][0] = Bb[(s4 * 8 + t) * 136 + col];
                    bb[nt][1] = Bb[(s4 * 8 + t + 4) * 136 + col];
                }
                #pragma unroll
                for (int mi = 0; mi < 2; ++mi)
                    #pragma unroll
                    for (int nt = 0; nt < 4; ++nt)
                        MMA16(acc[mi][nt], a[mi], bb[nt][0], bb[nt][1]);
            }
            if (ch < 7) {
                uint4* dst = reinterpret_cast<uint4*>(
                    smu + B_OFF + (buf ^ 1) * BBUF + pk2r * 136 + pn8);
                dst[0] = p0; dst[1] = p1;
            }
            __syncthreads();
        }

        #pragma unroll
        for (int nt = 0; nt < 4; ++nt) {
            const int cb = j0 + warp_n * 32 + nt * 8 + 2 * t;
            const float c20 = __ldg(&g_c2[cb]);
            const float c21 = __ldg(&g_c2[cb + 1]);
            #pragma unroll
            for (int mi = 0; mi < 2; ++mi) {
                #pragma unroll
                for (int h = 0; h < 2; ++h) {
                    const int s = mi * 2 + h;
                    #pragma unroll
                    for (int e = 0; e < 2; ++e) {
                        float v = fmaf(-2.f, acc[mi][nt][2 * h + e], e ? c21 : c20);
                        int c = cb + e;
                        if (v < sv2[s]) {
                            if (v < sv1[s]) {
                                sv2[s] = sv1[s]; si2[s] = si1[s];
                                sv1[s] = v; si1[s] = c;
                            } else { sv2[s] = v; si2[s] = c; }
                        }
                    }
                }
            }
        }
    }

    // ---- merge: alias reduction arrays over A smem region ----
    __syncthreads();
    float* V1 = (float*)smu;            // [16][64]
    float* V2 = V1 + 1024;
    int*   I1 = (int*)(V2 + 1024);
    int*   I2 = I1 + 1024;
    int*   labs = I2 + 1024;            // [64]
    float* lred = (float*)(labs + 64);  // [8]
    const int slot = warp_n * 4 + t;
    #pragma unroll
    for (int s = 0; s < 4; ++s) {
        int row = warp_m * 32 + (s >> 1) * 16 + (s & 1) * 8 + g;
        V1[slot * 64 + row] = sv1[s]; I1[slot * 64 + row] = si1[s];
        V2[slot * 64 + row] = sv2[s]; I2[slot * 64 + row] = si2[s];
    }
    __syncthreads();

    if (tid < 64) {
        float v1 = 3.4e38f, v2 = 3.4e38f; int i1 = 1 << 30;
        #pragma unroll
        for (int s = 0; s < 16; ++s) {
            float a1 = V1[s * 64 + tid], a2 = V2[s * 64 + tid];
            int   b1 = I1[s * 64 + tid];
            bool lt = (a1 < v1) || (a1 == v1 && b1 < i1);
            if (lt) { v2 = v1; v1 = a1; i1 = b1; } else if (a1 < v2) v2 = a1;
            if (a2 < v2) v2 = a2;
        }
        labels_out[row0 + tid] = (float)i1;
        labs[tid] = i1;
        if (v2 - v1 < M2) {
            int p = atomicAdd(&g_flagcnt, 1);
            g_flagrows[p] = row0 + tid;
            #pragma unroll
            for (int s = 0; s < 16; ++s) {
                g_cand[(size_t)p * 32 + s * 2 + 0] = (unsigned)I1[s * 64 + tid];
                g_cand[(size_t)p * 32 + s * 2 + 1] = (unsigned)I2[s * 64 + tid];
            }
        }
    }
    __syncthreads();

    // ---- fused scatter: exact loss + segment sums + counts ----
    float lsum = 0.f;
    #pragma unroll 1
    for (int r = 0; r < BM; ++r) {
        const int lab = labs[r];
        float x = emb[(size_t)(row0 + r) * DD + tid];
        float c = __ldg(&centers[(size_t)lab * DD + tid]);
        float d = x - c;
        lsum = fmaf(d, d, lsum);
        atomicAdd(&g_acc[(size_t)lab * DD + tid], x);
        if (tid == 0) atomicAdd(&g_cntf[lab], 1.0f);
    }
    #pragma unroll
    for (int o = 16; o > 0; o >>= 1) lsum += __shfl_down_sync(~0u, lsum, o);
    if (lane == 0) lred[wid] = lsum;
    __syncthreads();
    if (tid == 0) {
        float s = 0.f;
        #pragma unroll
        for (int w = 0; w < 8; ++w) s += lred[w];
        atomicAdd(&g_loss, s);
    }
}

// -------- exact fp32 rescore over 32 candidates; fix-list on change --------
__global__ void __launch_bounds__(256)
rescore_kernel(const float* __restrict__ emb, const float* __restrict__ centers,
               float* __restrict__ labels_out) {
    const int lane = threadIdx.x & 31, w = threadIdx.x >> 5;
    const int cnt = g_flagcnt;
    for (int fi = blockIdx.x * 8 + w; fi < cnt; fi += gridDim.x * 8) {
        const int row = g_flagrows[fi];
        const float4* xp = reinterpret_cast<const float4*>(emb + (size_t)row * DD);
        float4 x0 = __ldg(xp + 2 * lane);
        float4 x1 = __ldg(xp + 2 * lane + 1);
        float best = 3.4e38f; int bi = 1 << 30;
        #pragma unroll 1
        for (int q = 0; q < 32; ++q) {
            int c = (int)g_cand[(size_t)fi * 32 + q];
            const float4* cp = reinterpret_cast<const float4*>(centers + (size_t)c * DD);
            float4 c0 = __ldg(cp + 2 * lane);
            float4 c1 = __ldg(cp + 2 * lane + 1);
            float dot = x0.x * c0.x;
            dot = fmaf(x0.y, c0.y, dot); dot = fmaf(x0.z, c0.z, dot);
            dot = fmaf(x0.w, c0.w, dot); dot = fmaf(x1.x, c1.x, dot);
            dot = fmaf(x1.y, c1.y, dot); dot = fmaf(x1.z, c1.z, dot);
            dot = fmaf(x1.w, c1.w, dot);
            #pragma unroll
            for (int o = 16; o > 0; o >>= 1) dot += __shfl_xor_sync(~0u, dot, o);
            float v = fmaf(-2.f, dot, __ldg(&g_c2[c]));
            if (v < best || (v == best && c < bi)) { best = v; bi = c; }
        }
        if (lane == 0) {
            int old = (int)labels_out[row];
            if (bi != old) {
                int p = atomicAdd(&g_fixcnt, 1);
                g_fixrow[p] = row; g_fixold[p] = old;
                labels_out[row] = (float)bi;
            }
        }
    }
}

// -------- fix pass: move changed rows between centers, patch loss --------
__global__ void __launch_bounds__(256)
fix_kernel(const float* __restrict__ emb, const float* __restrict__ centers,
           const float* __restrict__ labels) {
    __shared__ float red[8];
    const int t = threadIdx.x;
    const int n = g_fixcnt;
    for (int e = blockIdx.x; e < n; e += gridDim.x) {
        const int row = g_fixrow[e];
        const int oldl = g_fixold[e];
        const int newl = (int)labels[row];
        float x = emb[(size_t)row * DD + t];
        float co = __ldg(&centers[(size_t)oldl * DD + t]);
        float cn = __ldg(&centers[(size_t)newl * DD + t]);
        atomicAdd(&g_acc[(size_t)oldl * DD + t], -x);
        atomicAdd(&g_acc[(size_t)newl * DD + t], x);
        float dn = x - cn, dd = x - co;
        float ls = dn * dn - dd * dd;
        #pragma unroll
        for (int o = 16; o > 0; o >>= 1) ls += __shfl_down_sync(~0u, ls, o);
        if ((t & 31) == 0) red[t >> 5] = ls;
        __syncthreads();
        if (t == 0) {
            float s = 0.f;
            #pragma unroll
            for (int w = 0; w < 8; ++w) s += red[w];
            atomicAdd(&g_loss, s);
            atomicAdd(&g_cntf[oldl], -1.0f);
            atomicAdd(&g_cntf[newl], 1.0f);
        }
        __syncthreads();
    }
}

__global__ void finalize_kernel(float* __restrict__ out) {
    int k = blockIdx.x, d = threadIdx.x;
    float cnt = g_cntf[k];
    out[(size_t)NN + (size_t)k * DD + d] = g_acc[(size_t)k * DD + d] / cnt;
    if (d == 0) out[(size_t)NN + (size_t)KK * DD + k] = cnt;
    if (k == 0 && d == 0) out[(size_t)NN + (size_t)KK * DD + KK] = g_loss / (float)NN;
}

extern "C" void kernel_launch(void* const* d_in, const int* in_sizes, int n_in,
                              void* d_out, int out_size) {
    const float* emb     = (const float*)d_in[0];
    const float* centers = (const float*)d_in[1];
    const int*   counts  = (const int*)d_in[2];
    float* out = (float*)d_out;

    cudaFuncSetAttribute(gemm_kernel, cudaFuncAttributeMaxDynamicSharedMemorySize, GEMM_SMEM);

    init_kernel<<<KK, 256>>>(centers, counts);
    gemm_kernel<<<NN / BM, 256, GEMM_SMEM>>>(emb, centers, out);
    rescore_kernel<<<1024, 256>>>(emb, centers, out);
    fix_kernel<<<128, 256>>>(emb, centers, out);
    finalize_kernel<<<KK, DD>>>(out);
}

// round 11
// speedup vs baseline: 2.5845x; 1.1262x over previous
#include <cuda_runtime.h>
#include <cuda_fp16.h>
#include <stdint.h>

#define NN 65536
#define DD 256
#define KK 4096
#define BM 64
#define BN 128
#define FCAP 65536
#define M2 1.25f

__device__ float g_acc[KK * DD];
__device__ float g_cntf[KK];
__device__ float g_c2[KK];
__device__ unsigned g_cbt[128 * KK];       // f16x2 centers, k2-major: [k2][n]
__device__ float g_loss;
__device__ int g_flagcnt;
__device__ int g_flagrows[FCAP];
__device__ int g_candn[FCAP];
__device__ unsigned g_cand[(size_t)FCAP * 32];
__device__ int g_fixcnt;
__device__ int g_fixrow[FCAP];
__device__ int g_fixold[FCAP];

__device__ __forceinline__ unsigned pack_h2(float lo, float hi) {
    __half2 h = __floats2half2_rn(lo, hi);
    return *reinterpret_cast<unsigned*>(&h);
}
__device__ __forceinline__ float2 unpack_h2(unsigned u) {
    __half2 h = *reinterpret_cast<__half2*>(&u);
    return __half22float2(h);
}

#define MMA16H(d, a, b0, b1)                                                   \
    asm volatile("mma.sync.aligned.m16n8k16.row.col.f16.f16.f16.f16 "         \
        "{%0,%1}, {%2,%3,%4,%5}, {%6,%7}, {%0,%1};"                           \
        : "+r"((d)[0]), "+r"((d)[1])                                          \
        : "r"((a).x), "r"((a).y), "r"((a).z), "r"((a).w), "r"(b0), "r"(b1))

// ------------------------------- init -------------------------------
__global__ void init_kernel(const float* __restrict__ centers,
                            const int* __restrict__ counts) {
    int k = blockIdx.x, d = threadIdx.x;
    __shared__ float cs[DD];
    float c = centers[(size_t)k * DD + d];
    float cnt = (float)counts[k];
    g_acc[(size_t)k * DD + d] = cnt * c;
    cs[d] = c;
    __shared__ float red[8];
    float v = c * c;
    #pragma unroll
    for (int o = 16; o > 0; o >>= 1) v += __shfl_down_sync(~0u, v, o);
    if ((d & 31) == 0) red[d >> 5] = v;
    __syncthreads();
    if (d < 128)
        g_cbt[(size_t)d * KK + k] = pack_h2(cs[2 * d], cs[2 * d + 1]);
    if (d == 0) {
        float s = 0.f;
        #pragma unroll
        for (int w = 0; w < 8; ++w) s += red[w];
        g_c2[k] = s; g_cntf[k] = cnt;
        if (k == 0) { g_loss = 0.f; g_flagcnt = 0; g_fixcnt = 0; }
    }
}

// --- f16 mma.sync GEMM (f16 accum) + top-2 argmin + fused scatter, occ 3 ---
#define B_OFF 8192
#define BBUF 2176
#define SMEM_U32 (B_OFF + 2 * BBUF)
#define GEMM_SMEM (SMEM_U32 * 4)

__global__ void __launch_bounds__(256, 3)
gemm_kernel(const float* __restrict__ emb, const float* __restrict__ centers,
            float* __restrict__ labels_out) {
    extern __shared__ unsigned smu[];
    const int tid = threadIdx.x, lane = tid & 31, wid = tid >> 5;
    const int warp_m = wid >> 2, warp_n = wid & 3;   // 2 x 4 warp grid
    const int g = lane >> 2, t = lane & 3;
    const int row0 = blockIdx.x * BM;

    // ---- stage A: f16 fragment-major, 64 rows ----
    #pragma unroll 4
    for (int it = 0; it < 16; ++it) {
        int i = it * 256 + tid;
        int m = i >> 6, kq = i & 63;
        float4 v = *reinterpret_cast<const float4*>(emb + (size_t)(row0 + m) * DD + kq * 4);
        unsigned w0 = pack_h2(v.x, v.y), w1 = pack_h2(v.z, v.w);
        int rr = m & 15, mt = m >> 4;
        #pragma unroll
        for (int hh = 0; hh < 2; ++hh) {
            int k2 = 2 * kq + hh;
            int sg = k2 >> 3, kw = k2 & 7;
            int L = (rr & 7) * 4 + (kw & 3);
            int j = (rr >> 3) + 2 * (kw >> 2);
            smu[((sg * 4 + mt) * 32 + L) * 4 + j] = hh ? w1 : w0;
        }
    }

    float sv1[4], sv2[4]; int si1[4], si2[4];
    #pragma unroll
    for (int s = 0; s < 4; ++s) { sv1[s] = sv2[s] = 3.4e38f; si1[s] = si2[s] = 0; }
    __syncthreads();

    const int pk2r = tid >> 4, pn8 = (tid & 15) * 8;

    #pragma unroll 1
    for (int tile = 0; tile < KK / BN; ++tile) {
        const int j0 = tile * BN;
        unsigned acc[2][4][2];
        #pragma unroll
        for (int a = 0; a < 2; ++a)
            #pragma unroll
            for (int b = 0; b < 4; ++b) { acc[a][b][0] = 0u; acc[a][b][1] = 0u; }

        uint4 p0, p1;
        {
            const uint4* src = reinterpret_cast<const uint4*>(
                g_cbt + (size_t)pk2r * KK + j0 + pn8);
            p0 = src[0]; p1 = src[1];
            uint4* dst = reinterpret_cast<uint4*>(smu + B_OFF + pk2r * 136 + pn8);
            dst[0] = p0; dst[1] = p1;
        }
        __syncthreads();

        #pragma unroll 1
        for (int ch = 0; ch < 8; ++ch) {
            const int buf = ch & 1;
            if (ch < 7) {
                const uint4* src = reinterpret_cast<const uint4*>(
                    g_cbt + (size_t)((ch + 1) * 16 + pk2r) * KK + j0 + pn8);
                p0 = src[0]; p1 = src[1];
            }
            const unsigned* Bb = smu + B_OFF + buf * BBUF;
            #pragma unroll
            for (int s4 = 0; s4 < 2; ++s4) {
                const int sg = ch * 2 + s4;
                uint4 a[2];
                #pragma unroll
                for (int mi = 0; mi < 2; ++mi)
                    a[mi] = *(reinterpret_cast<const uint4*>(smu) +
                              ((sg * 4 + warp_m * 2 + mi) * 32 + lane));
                unsigned bb[4][2];
                #pragma unroll
                for (int nt = 0; nt < 4; ++nt) {
                    int col = warp_n * 32 + nt * 8 + g;
                    bb[nt][0] = Bb[(s4 * 8 + t) * 136 + col];
                    bb[nt][1] = Bb[(s4 * 8 + t + 4) * 136 + col];
                }
                #pragma unroll
                for (int mi = 0; mi < 2; ++mi)
                    #pragma unroll
                    for (int nt = 0; nt < 4; ++nt)
                        MMA16H(acc[mi][nt], a[mi], bb[nt][0], bb[nt][1]);
            }
            if (ch < 7) {
                uint4* dst = reinterpret_cast<uint4*>(
                    smu + B_OFF + (buf ^ 1) * BBUF + pk2r * 136 + pn8);
                dst[0] = p0; dst[1] = p1;
            }
            __syncthreads();
        }

        // per-tile epilogue: v = c2 - 2*dot, top-2 insert per row-slot
        #pragma unroll
        for (int nt = 0; nt < 4; ++nt) {
            const int cb = j0 + warp_n * 32 + nt * 8 + 2 * t;
            const float c20 = __ldg(&g_c2[cb]);
            const float c21 = __ldg(&g_c2[cb + 1]);
            #pragma unroll
            for (int mi = 0; mi < 2; ++mi) {
                #pragma unroll
                for (int h = 0; h < 2; ++h) {
                    const int s = mi * 2 + h;
                    float2 f = unpack_h2(acc[mi][nt][h]);
                    #pragma unroll
                    for (int e = 0; e < 2; ++e) {
                        float v = fmaf(-2.f, e ? f.y : f.x, e ? c21 : c20);
                        int c = cb + e;
                        if (v < sv2[s]) {
                            if (v < sv1[s]) {
                                sv2[s] = sv1[s]; si2[s] = si1[s];
                                sv1[s] = v; si1[s] = c;
                            } else { sv2[s] = v; si2[s] = c; }
                        }
                    }
                }
            }
        }
    }

    // ---- merge: alias reduction arrays over A smem region ----
    __syncthreads();
    float* V1 = (float*)smu;            // [16][64]
    float* V2 = V1 + 1024;
    int*   I1 = (int*)(V2 + 1024);
    int*   I2 = I1 + 1024;
    int*   labs = I2 + 1024;            // [64]
    float* lred = (float*)(labs + 64);  // [8]
    const int slot = warp_n * 4 + t;
    #pragma unroll
    for (int s = 0; s < 4; ++s) {
        int row = warp_m * 32 + (s >> 1) * 16 + (s & 1) * 8 + g;
        V1[slot * 64 + row] = sv1[s]; I1[slot * 64 + row] = si1[s];
        V2[slot * 64 + row] = sv2[s]; I2[slot * 64 + row] = si2[s];
    }
    __syncthreads();

    if (tid < 64) {
        float v1 = 3.4e38f, v2 = 3.4e38f; int i1 = 1 << 30;
        #pragma unroll
        for (int s = 0; s < 16; ++s) {
            float a1 = V1[s * 64 + tid], a2 = V2[s * 64 + tid];
            int   b1 = I1[s * 64 + tid];
            bool lt = (a1 < v1) || (a1 == v1 && b1 < i1);
            if (lt) { v2 = v1; v1 = a1; i1 = b1; } else if (a1 < v2) v2 = a1;
            if (a2 < v2) v2 = a2;
        }
        labels_out[row0 + tid] = (float)i1;
        labs[tid] = i1;
        if (v2 - v1 < M2) {
            int p = atomicAdd(&g_flagcnt, 1);
            g_flagrows[p] = row0 + tid;
            const float thr = v1 + M2;
            int nc = 0;
            #pragma unroll
            for (int s = 0; s < 16; ++s) {
                if (V1[s * 64 + tid] < thr)
                    g_cand[(size_t)p * 32 + nc++] = (unsigned)I1[s * 64 + tid];
                if (V2[s * 64 + tid] < thr)
                    g_cand[(size_t)p * 32 + nc++] = (unsigned)I2[s * 64 + tid];
            }
            g_candn[p] = nc;
        }
    }
    __syncthreads();

    // ---- fused scatter: exact loss + segment sums + counts ----
    float lsum = 0.f;
    #pragma unroll 1
    for (int r = 0; r < BM; ++r) {
        const int lab = labs[r];
        float x = emb[(size_t)(row0 + r) * DD + tid];
        float c = __ldg(&centers[(size_t)lab * DD + tid]);
        float d = x - c;
        lsum = fmaf(d, d, lsum);
        atomicAdd(&g_acc[(size_t)lab * DD + tid], x);
        if (tid == 0) atomicAdd(&g_cntf[lab], 1.0f);
    }
    #pragma unroll
    for (int o = 16; o > 0; o >>= 1) lsum += __shfl_down_sync(~0u, lsum, o);
    if (lane == 0) lred[wid] = lsum;
    __syncthreads();
    if (tid == 0) {
        float s = 0.f;
        #pragma unroll
        for (int w = 0; w < 8; ++w) s += lred[w];
        atomicAdd(&g_loss, s);
    }
}

// ---- exact fp32 rescore over filtered candidates; fix-list on change ----
__global__ void __launch_bounds__(256)
rescore_kernel(const float* __restrict__ emb, const float* __restrict__ centers,
               float* __restrict__ labels_out) {
    const int lane = threadIdx.x & 31, w = threadIdx.x >> 5;
    const int cnt = g_flagcnt;
    for (int fi = blockIdx.x * 8 + w; fi < cnt; fi += gridDim.x * 8) {
        const int row = g_flagrows[fi];
        const int nc = g_candn[fi];
        const float4* xp = reinterpret_cast<const float4*>(emb + (size_t)row * DD);
        float4 x0 = __ldg(xp + 2 * lane);
        float4 x1 = __ldg(xp + 2 * lane + 1);
        float best = 3.4e38f; int bi = 1 << 30;
        #pragma unroll 1
        for (int q = 0; q < nc; ++q) {
            int c = (int)g_cand[(size_t)fi * 32 + q];
            const float4* cp = reinterpret_cast<const float4*>(centers + (size_t)c * DD);
            float4 c0 = __ldg(cp + 2 * lane);
            float4 c1 = __ldg(cp + 2 * lane + 1);
            float dot = x0.x * c0.x;
            dot = fmaf(x0.y, c0.y, dot); dot = fmaf(x0.z, c0.z, dot);
            dot = fmaf(x0.w, c0.w, dot); dot = fmaf(x1.x, c1.x, dot);
            dot = fmaf(x1.y, c1.y, dot); dot = fmaf(x1.z, c1.z, dot);
            dot = fmaf(x1.w, c1.w, dot);
            #pragma unroll
            for (int o = 16; o > 0; o >>= 1) dot += __shfl_xor_sync(~0u, dot, o);
            float v = fmaf(-2.f, dot, __ldg(&g_c2[c]));
            if (v < best || (v == best && c < bi)) { best = v; bi = c; }
        }
        if (lane == 0) {
            int old = (int)labels_out[row];
            if (bi != old) {
                int p = atomicAdd(&g_fixcnt, 1);
                g_fixrow[p] = row; g_fixold[p] = old;
                labels_out[row] = (float)bi;
            }
        }
    }
}

// -------- fix pass: move changed rows between centers, patch loss --------
__global__ void __launch_bounds__(256)
fix_kernel(const float* __restrict__ emb, const float* __restrict__ centers,
           const float* __restrict__ labels) {
    __shared__ float red[8];
    const int t = threadIdx.x;
    const int n = g_fixcnt;
    for (int e = blockIdx.x; e < n; e += gridDim.x) {
        const int row = g_fixrow[e];
        const int oldl = g_fixold[e];
        const int newl = (int)labels[row];
        float x = emb[(size_t)row * DD + t];
        float co = __ldg(&centers[(size_t)oldl * DD + t]);
        float cn = __ldg(&centers[(size_t)newl * DD + t]);
        atomicAdd(&g_acc[(size_t)oldl * DD + t], -x);
        atomicAdd(&g_acc[(size_t)newl * DD + t], x);
        float dn = x - cn, dd = x - co;
        float ls = dn * dn - dd * dd;
        #pragma unroll
        for (int o = 16; o > 0; o >>= 1) ls += __shfl_down_sync(~0u, ls, o);
        if ((t & 31) == 0) red[t >> 5] = ls;
        __syncthreads();
        if (t == 0) {
            float s = 0.f;
            #pragma unroll
            for (int w = 0; w < 8; ++w) s += red[w];
            atomicAdd(&g_loss, s);
            atomicAdd(&g_cntf[oldl], -1.0f);
            atomicAdd(&g_cntf[newl], 1.0f);
        }
        __syncthreads();
    }
}

__global__ void finalize_kernel(float* __restrict__ out) {
    int k = blockIdx.x, d = threadIdx.x;
    float cnt = g_cntf[k];
    out[(size_t)NN + (size_t)k * DD + d] = g_acc[(size_t)k * DD + d] / cnt;
    if (d == 0) out[(size_t)NN + (size_t)KK * DD + k] = cnt;
    if (k == 0 && d == 0) out[(size_t)NN + (size_t)KK * DD + KK] = g_loss / (float)NN;
}

extern "C" void kernel_launch(void* const* d_in, const int* in_sizes, int n_in,
                              void* d_out, int out_size) {
    const float* emb     = (const float*)d_in[0];
    const float* centers = (const float*)d_in[1];
    const int*   counts  = (const int*)d_in[2];
    float* out = (float*)d_out;

    cudaFuncSetAttribute(gemm_kernel, cudaFuncAttributeMaxDynamicSharedMemorySize, GEMM_SMEM);

    init_kernel<<<KK, 256>>>(centers, counts);
    gemm_kernel<<<NN / BM, 256, GEMM_SMEM>>>(emb, centers, out);
    rescore_kernel<<<1024, 256>>>(emb, centers, out);
    fix_kernel<<<128, 256>>>(emb, centers, out);
    finalize_kernel<<<KK, DD>>>(out);
}